// round 7
// baseline (speedup 1.0000x reference)
#include <cuda_runtime.h>
#include <math.h>

#define BATCH  4
#define SEQ    2048
#define EMBED  256
#define HIDDEN 512
#define ROWS   (BATCH * SEQ)   // 8192

// -------- scratch (allocation-free: __device__ globals) --------
__device__ float g_act[ROWS * HIDDEN];                    // 16 MB
__device__ float g_q[ROWS * HIDDEN];                      // 16 MB
__device__ float g_k[ROWS * HIDDEN];                      // 16 MB
__device__ float g_v[ROWS * HIDDEN];                      // 16 MB
__device__ float g_scores[(size_t)BATCH * SEQ * SEQ];     // 64 MB

// ============================================================
// Kernel 1: act = gelu( emb_table[tok] @ W1 + b1 )
// M=8192, K=256, N=512. 64x64 tile, 4x4 micro, BK=16.
// ============================================================
__global__ void embed_mlp_kernel(const int* __restrict__ tok,
                                 const float* __restrict__ emb,
                                 const float* __restrict__ W1,
                                 const float* __restrict__ b1)
{
    __shared__ float As[64][17];
    __shared__ float Bs[16][64];

    const int tile_n = blockIdx.x * 64;
    const int tile_m = blockIdx.y * 64;
    const int t  = threadIdx.x;        // 0..255
    const int tx = t & 15;
    const int ty = t >> 4;

    float acc[4][4] = {};

    for (int k0 = 0; k0 < EMBED; k0 += 16) {
        #pragma unroll
        for (int i = 0; i < 4; i++) {
            int idx = t + i * 256;
            int r = idx >> 4, c = idx & 15;
            int token = tok[tile_m + r];
            As[r][c] = emb[(size_t)token * EMBED + k0 + c];
        }
        #pragma unroll
        for (int i = 0; i < 4; i++) {
            int idx = t + i * 256;
            int r = idx >> 6, c = idx & 63;
            Bs[r][c] = W1[(k0 + r) * HIDDEN + tile_n + c];
        }
        __syncthreads();
        #pragma unroll
        for (int kk = 0; kk < 16; kk++) {
            float a[4], b[4];
            #pragma unroll
            for (int i = 0; i < 4; i++) a[i] = As[ty * 4 + i][kk];
            #pragma unroll
            for (int j = 0; j < 4; j++) b[j] = Bs[kk][tx * 4 + j];
            #pragma unroll
            for (int i = 0; i < 4; i++)
                #pragma unroll
                for (int j = 0; j < 4; j++)
                    acc[i][j] = fmaf(a[i], b[j], acc[i][j]);
        }
        __syncthreads();
    }

    #pragma unroll
    for (int i = 0; i < 4; i++) {
        int row = tile_m + ty * 4 + i;
        #pragma unroll
        for (int j = 0; j < 4; j++) {
            int col = tile_n + tx * 4 + j;
            float x = acc[i][j] + b1[col];
            // exact GELU: 0.5*x*(1+erf(x/sqrt(2)))
            float g = 0.5f * x * (1.0f + erff(x * 0.7071067811865475f));
            g_act[(size_t)row * HIDDEN + col] = g;
        }
    }
}

// ============================================================
// Kernel 2: q/k/v = act @ W{q,k,v} + b{q,k,v}   (blockIdx.z selects)
// M=8192, K=512, N=512.
// ============================================================
__global__ void qkv_kernel(const float* __restrict__ Wq, const float* __restrict__ bq,
                           const float* __restrict__ Wk, const float* __restrict__ bk,
                           const float* __restrict__ Wv, const float* __restrict__ bv)
{
    __shared__ float As[64][17];
    __shared__ float Bs[16][64];

    const float* W; const float* bias; float* out;
    if      (blockIdx.z == 0) { W = Wq; bias = bq; out = g_q; }
    else if (blockIdx.z == 1) { W = Wk; bias = bk; out = g_k; }
    else                      { W = Wv; bias = bv; out = g_v; }

    const int tile_n = blockIdx.x * 64;
    const int tile_m = blockIdx.y * 64;
    const int t  = threadIdx.x;
    const int tx = t & 15;
    const int ty = t >> 4;

    float acc[4][4] = {};

    for (int k0 = 0; k0 < HIDDEN; k0 += 16) {
        #pragma unroll
        for (int i = 0; i < 4; i++) {
            int idx = t + i * 256;
            int r = idx >> 4, c = idx & 15;
            As[r][c] = g_act[(size_t)(tile_m + r) * HIDDEN + k0 + c];
        }
        #pragma unroll
        for (int i = 0; i < 4; i++) {
            int idx = t + i * 256;
            int r = idx >> 6, c = idx & 63;
            Bs[r][c] = W[(k0 + r) * HIDDEN + tile_n + c];
        }
        __syncthreads();
        #pragma unroll
        for (int kk = 0; kk < 16; kk++) {
            float a[4], b[4];
            #pragma unroll
            for (int i = 0; i < 4; i++) a[i] = As[ty * 4 + i][kk];
            #pragma unroll
            for (int j = 0; j < 4; j++) b[j] = Bs[kk][tx * 4 + j];
            #pragma unroll
            for (int i = 0; i < 4; i++)
                #pragma unroll
                for (int j = 0; j < 4; j++)
                    acc[i][j] = fmaf(a[i], b[j], acc[i][j]);
        }
        __syncthreads();
    }

    #pragma unroll
    for (int i = 0; i < 4; i++) {
        int row = tile_m + ty * 4 + i;
        #pragma unroll
        for (int j = 0; j < 4; j++) {
            int col = tile_n + tx * 4 + j;
            out[(size_t)row * HIDDEN + col] = acc[i][j] + bias[col];
        }
    }
}

// ============================================================
// Kernel 3: scores[b,s,t] = dot(q[b,s,:], k[b,t,:]) / sqrt(512)
// Per batch z: M=2048 (s), N=2048 (t), K=512 (h). Both operands K-major.
// ============================================================
__global__ void scores_kernel()
{
    __shared__ float Qs[64][17];
    __shared__ float Ks[64][17];

    const int z = blockIdx.z;
    const float* Q = g_q + (size_t)z * SEQ * HIDDEN;
    const float* K = g_k + (size_t)z * SEQ * HIDDEN;
    float* C = g_scores + (size_t)z * SEQ * SEQ;

    const int tile_n = blockIdx.x * 64;   // t
    const int tile_m = blockIdx.y * 64;   // s
    const int t  = threadIdx.x;
    const int tx = t & 15;
    const int ty = t >> 4;

    float acc[4][4] = {};

    for (int k0 = 0; k0 < HIDDEN; k0 += 16) {
        #pragma unroll
        for (int i = 0; i < 4; i++) {
            int idx = t + i * 256;
            int r = idx >> 4, c = idx & 15;
            Qs[r][c] = Q[(size_t)(tile_m + r) * HIDDEN + k0 + c];
            Ks[r][c] = K[(size_t)(tile_n + r) * HIDDEN + k0 + c];
        }
        __syncthreads();
        #pragma unroll
        for (int kk = 0; kk < 16; kk++) {
            float a[4], b[4];
            #pragma unroll
            for (int i = 0; i < 4; i++) a[i] = Qs[ty * 4 + i][kk];
            #pragma unroll
            for (int j = 0; j < 4; j++) b[j] = Ks[tx * 4 + j][kk];
            #pragma unroll
            for (int i = 0; i < 4; i++)
                #pragma unroll
                for (int j = 0; j < 4; j++)
                    acc[i][j] = fmaf(a[i], b[j], acc[i][j]);
        }
        __syncthreads();
    }

    const float scale = 0.04419417382415922f;   // 1/sqrt(512)
    #pragma unroll
    for (int i = 0; i < 4; i++) {
        int row = tile_m + ty * 4 + i;
        #pragma unroll
        for (int j = 0; j < 4; j++) {
            int col = tile_n + tx * 4 + j;
            C[(size_t)row * SEQ + col] = acc[i][j] * scale;
        }
    }
}

// ============================================================
// Kernel 4: row softmax over g_scores (8192 rows x 2048)
// ============================================================
__global__ void softmax_kernel()
{
    const int row = blockIdx.x;
    float* p = g_scores + (size_t)row * SEQ;
    const int t = threadIdx.x;       // 256 threads, 8 elems each
    __shared__ float red[16];

    float v[8];
    float lmax = -1e30f;
    #pragma unroll
    for (int i = 0; i < 8; i++) {
        v[i] = p[t + i * 256];
        lmax = fmaxf(lmax, v[i]);
    }
    #pragma unroll
    for (int o = 16; o; o >>= 1)
        lmax = fmaxf(lmax, __shfl_xor_sync(0xffffffffu, lmax, o));
    if ((t & 31) == 0) red[t >> 5] = lmax;
    __syncthreads();
    float rmax = red[0];
    #pragma unroll
    for (int i = 1; i < 8; i++) rmax = fmaxf(rmax, red[i]);

    float lsum = 0.0f;
    #pragma unroll
    for (int i = 0; i < 8; i++) {
        v[i] = __expf(v[i] - rmax);
        lsum += v[i];
    }
    #pragma unroll
    for (int o = 16; o; o >>= 1)
        lsum += __shfl_xor_sync(0xffffffffu, lsum, o);
    if ((t & 31) == 0) red[8 + (t >> 5)] = lsum;
    __syncthreads();
    float total = 0.0f;
    #pragma unroll
    for (int i = 0; i < 8; i++) total += red[8 + i];

    float inv = 1.0f / total;
    #pragma unroll
    for (int i = 0; i < 8; i++)
        p[t + i * 256] = v[i] * inv;
}

// ============================================================
// Kernel 5: out[b,s,:] = attn[b,s,:] @ v[b,:,:]
// Per batch z: M=2048, N=512, K=2048.
// ============================================================
__global__ void out_kernel(float* __restrict__ out)
{
    __shared__ float As[64][17];
    __shared__ float Bs[16][64];

    const int z = blockIdx.z;
    const float* A = g_scores + (size_t)z * SEQ * SEQ;
    const float* V = g_v + (size_t)z * SEQ * HIDDEN;
    float* C = out + (size_t)z * SEQ * HIDDEN;

    const int tile_n = blockIdx.x * 64;
    const int tile_m = blockIdx.y * 64;
    const int t  = threadIdx.x;
    const int tx = t & 15;
    const int ty = t >> 4;

    float acc[4][4] = {};

    for (int k0 = 0; k0 < SEQ; k0 += 16) {
        #pragma unroll
        for (int i = 0; i < 4; i++) {
            int idx = t + i * 256;
            int r = idx >> 4, c = idx & 15;
            As[r][c] = A[(size_t)(tile_m + r) * SEQ + k0 + c];
        }
        #pragma unroll
        for (int i = 0; i < 4; i++) {
            int idx = t + i * 256;
            int r = idx >> 6, c = idx & 63;
            Bs[r][c] = V[(size_t)(k0 + r) * HIDDEN + tile_n + c];
        }
        __syncthreads();
        #pragma unroll
        for (int kk = 0; kk < 16; kk++) {
            float a[4], b[4];
            #pragma unroll
            for (int i = 0; i < 4; i++) a[i] = As[ty * 4 + i][kk];
            #pragma unroll
            for (int j = 0; j < 4; j++) b[j] = Bs[kk][tx * 4 + j];
            #pragma unroll
            for (int i = 0; i < 4; i++)
                #pragma unroll
                for (int j = 0; j < 4; j++)
                    acc[i][j] = fmaf(a[i], b[j], acc[i][j]);
        }
        __syncthreads();
    }

    #pragma unroll
    for (int i = 0; i < 4; i++) {
        int row = tile_m + ty * 4 + i;
        #pragma unroll
        for (int j = 0; j < 4; j++) {
            int col = tile_n + tx * 4 + j;
            C[(size_t)row * HIDDEN + col] = acc[i][j];
        }
    }
}

// ============================================================
// launch
// ============================================================
extern "C" void kernel_launch(void* const* d_in, const int* in_sizes, int n_in,
                              void* d_out, int out_size)
{
    const int*   tok = (const int*)  d_in[0];
    const float* emb = (const float*)d_in[1];
    const float* W1  = (const float*)d_in[2];
    const float* b1  = (const float*)d_in[3];
    const float* Wq  = (const float*)d_in[4];
    const float* bq  = (const float*)d_in[5];
    const float* Wk  = (const float*)d_in[6];
    const float* bk  = (const float*)d_in[7];
    const float* Wv  = (const float*)d_in[8];
    const float* bv  = (const float*)d_in[9];
    float* out = (float*)d_out;

    dim3 blk(256);
    embed_mlp_kernel<<<dim3(HIDDEN / 64, ROWS / 64), blk>>>(tok, emb, W1, b1);
    qkv_kernel<<<dim3(HIDDEN / 64, ROWS / 64, 3), blk>>>(Wq, bq, Wk, bk, Wv, bv);
    scores_kernel<<<dim3(SEQ / 64, SEQ / 64, BATCH), blk>>>();
    softmax_kernel<<<dim3(ROWS), blk>>>();
    out_kernel<<<dim3(HIDDEN / 64, SEQ / 64, BATCH), blk>>>(out);
}

// round 10
// speedup vs baseline: 2.3285x; 2.3285x over previous
#include <cuda_runtime.h>
#include <cuda_bf16.h>
#include <math.h>
#include <stdint.h>

#define BATCH  4
#define SEQ    2048
#define EMBED  256
#define HIDDEN 512
#define ROWS   (BATCH * SEQ)   // 8192

// -------- scratch (allocation-free: __device__ globals) --------
__device__ __align__(16) __nv_bfloat16 g_acth[ROWS * HIDDEN];            // 8 MB
__device__ __align__(16) __nv_bfloat16 g_actl[ROWS * HIDDEN];
__device__ __align__(16) __nv_bfloat16 g_wth[3 * HIDDEN * HIDDEN];       // W^T hi  [z][n][k]
__device__ __align__(16) __nv_bfloat16 g_wtl[3 * HIDDEN * HIDDEN];
__device__ __align__(16) __nv_bfloat16 g_qh[ROWS * HIDDEN];
__device__ __align__(16) __nv_bfloat16 g_ql[ROWS * HIDDEN];
__device__ __align__(16) __nv_bfloat16 g_kh[ROWS * HIDDEN];
__device__ __align__(16) __nv_bfloat16 g_kl[ROWS * HIDDEN];
__device__ __align__(16) __nv_bfloat16 g_vth[BATCH * HIDDEN * SEQ];      // V^T [b][h][s]
__device__ __align__(16) __nv_bfloat16 g_vtl[BATCH * HIDDEN * SEQ];
__device__ float g_scores[(size_t)BATCH * SEQ * SEQ];                    // 64 MB
__device__ __align__(16) __nv_bfloat16 g_ah[(size_t)BATCH * SEQ * SEQ];  // attn hi
__device__ __align__(16) __nv_bfloat16 g_al[(size_t)BATCH * SEQ * SEQ];  // attn lo

__device__ __forceinline__ void bf16_split(float x, __nv_bfloat16& h, __nv_bfloat16& l) {
    h = __float2bfloat16_rn(x);
    l = __float2bfloat16_rn(x - __bfloat162float(h));
}

// ============================================================
// Kernel 1: act = gelu( emb_table[tok] @ W1 + b1 )  (fp32 SIMT, epi -> bf16 hi/lo)
// ============================================================
__global__ void embed_mlp_kernel(const int* __restrict__ tok,
                                 const float* __restrict__ emb,
                                 const float* __restrict__ W1,
                                 const float* __restrict__ b1)
{
    __shared__ float As[64][17];
    __shared__ float Bs[16][64];

    const int tile_n = blockIdx.x * 64;
    const int tile_m = blockIdx.y * 64;
    const int t  = threadIdx.x;
    const int tx = t & 15;
    const int ty = t >> 4;

    float acc[4][4] = {};

    for (int k0 = 0; k0 < EMBED; k0 += 16) {
        #pragma unroll
        for (int i = 0; i < 4; i++) {
            int idx = t + i * 256;
            int r = idx >> 4, c = idx & 15;
            int token = tok[tile_m + r];
            As[r][c] = emb[(size_t)token * EMBED + k0 + c];
        }
        #pragma unroll
        for (int i = 0; i < 4; i++) {
            int idx = t + i * 256;
            int r = idx >> 6, c = idx & 63;
            Bs[r][c] = W1[(k0 + r) * HIDDEN + tile_n + c];
        }
        __syncthreads();
        #pragma unroll
        for (int kk = 0; kk < 16; kk++) {
            float a[4], b[4];
            #pragma unroll
            for (int i = 0; i < 4; i++) a[i] = As[ty * 4 + i][kk];
            #pragma unroll
            for (int j = 0; j < 4; j++) b[j] = Bs[kk][tx * 4 + j];
            #pragma unroll
            for (int i = 0; i < 4; i++)
                #pragma unroll
                for (int j = 0; j < 4; j++)
                    acc[i][j] = fmaf(a[i], b[j], acc[i][j]);
        }
        __syncthreads();
    }

    #pragma unroll
    for (int i = 0; i < 4; i++) {
        int row = tile_m + ty * 4 + i;
        #pragma unroll
        for (int j = 0; j < 4; j++) {
            int col = tile_n + tx * 4 + j;
            float x = acc[i][j] + b1[col];
            float g = 0.5f * x * (1.0f + erff(x * 0.7071067811865475f));
            __nv_bfloat16 h, l;
            bf16_split(g, h, l);
            size_t o = (size_t)row * HIDDEN + col;
            g_acth[o] = h; g_actl[o] = l;
        }
    }
}

// ============================================================
// Kernel 1b: transpose + hi/lo split of Wq/Wk/Wv -> g_wt{h,l}[z][n][k]
// ============================================================
__global__ void wsplit_kernel(const float* __restrict__ Wq,
                              const float* __restrict__ Wk,
                              const float* __restrict__ Wv)
{
    const int z = blockIdx.z;
    const float* W = (z == 0) ? Wq : (z == 1) ? Wk : Wv;
    int idx = blockIdx.x * 256 + threadIdx.x;       // over 512*512
    int n = idx >> 9, k = idx & 511;
    float x = W[k * HIDDEN + n];
    __nv_bfloat16 h, l;
    bf16_split(x, h, l);
    size_t o = (size_t)z * HIDDEN * HIDDEN + (size_t)n * HIDDEN + k;
    g_wth[o] = h; g_wtl[o] = l;
}

// ============================================================
// Warp-MMA GEMM core (legacy mma.sync m16n8k16 bf16, fp32 acc, hi/lo split)
// C tile 128x128, 256 threads = 8 warps (2 m x 4 n), warp tile 64x32.
// A: [128, K] K-major bf16 (hi,lo).  B: [128(N), K] K-major bf16 (hi,lo).
// K-chunk 32 through padded smem (stride 40 bf16 -> conflict-free b32 loads).
// ============================================================
#define KC     32
#define SPITCH 40

__device__ __forceinline__ void mma16816(float c[4], const uint32_t a[4], const uint32_t b[2]) {
    asm volatile(
        "mma.sync.aligned.m16n8k16.row.col.f32.bf16.bf16.f32 "
        "{%0,%1,%2,%3}, {%4,%5,%6,%7}, {%8,%9}, {%0,%1,%2,%3};"
        : "+f"(c[0]), "+f"(c[1]), "+f"(c[2]), "+f"(c[3])
        : "r"(a[0]), "r"(a[1]), "r"(a[2]), "r"(a[3]), "r"(b[0]), "r"(b[1]));
}

__device__ __forceinline__ void ldfragA(const __nv_bfloat16 (*sA)[SPITCH],
                                        int m0, int kk, int g, int tg, uint32_t a[4]) {
    a[0] = *(const uint32_t*)&sA[m0 + g    ][kk +     tg * 2];
    a[1] = *(const uint32_t*)&sA[m0 + g + 8][kk +     tg * 2];
    a[2] = *(const uint32_t*)&sA[m0 + g    ][kk + 8 + tg * 2];
    a[3] = *(const uint32_t*)&sA[m0 + g + 8][kk + 8 + tg * 2];
}
__device__ __forceinline__ void ldfragB(const __nv_bfloat16 (*sB)[SPITCH],
                                        int n0, int kk, int g, int tg, uint32_t b[2]) {
    b[0] = *(const uint32_t*)&sB[n0 + g][kk +     tg * 2];
    b[1] = *(const uint32_t*)&sB[n0 + g][kk + 8 + tg * 2];
}

__device__ __forceinline__ void copy_tile(const __nv_bfloat16* __restrict__ src, size_t ld,
                                          __nv_bfloat16 (*dst)[SPITCH], int t)
{
    // 128 rows x 32 bf16 = 512 x 16B chunks; 256 threads x 2
    #pragma unroll
    for (int i = 0; i < 2; i++) {
        int idx = t + i * 256;
        int r = idx >> 2, c = idx & 3;
        uint4 v = *reinterpret_cast<const uint4*>(src + (size_t)r * ld + c * 8);
        *reinterpret_cast<uint4*>(&dst[r][c * 8]) = v;
    }
}

template <class Epi>
__device__ __forceinline__ void gemm_mma_body(
    const __nv_bfloat16* __restrict__ Ah, const __nv_bfloat16* __restrict__ Al, size_t lda,
    const __nv_bfloat16* __restrict__ Bh, const __nv_bfloat16* __restrict__ Bl, size_t ldb,
    int K, Epi epi)
{
    __shared__ __align__(16) __nv_bfloat16 sAh[128][SPITCH];
    __shared__ __align__(16) __nv_bfloat16 sAl[128][SPITCH];
    __shared__ __align__(16) __nv_bfloat16 sBh[128][SPITCH];
    __shared__ __align__(16) __nv_bfloat16 sBl[128][SPITCH];

    const int t    = threadIdx.x;
    const int lane = t & 31;
    const int wid  = t >> 5;
    const int wm   = (wid & 1) * 64;      // warp m-offset
    const int wn   = (wid >> 1) * 32;     // warp n-offset
    const int g    = lane >> 2;
    const int tg   = lane & 3;

    float acc[4][4][4] = {};

    for (int k0 = 0; k0 < K; k0 += KC) {
        copy_tile(Ah + k0, lda, sAh, t);
        copy_tile(Al + k0, lda, sAl, t);
        copy_tile(Bh + k0, ldb, sBh, t);
        copy_tile(Bl + k0, ldb, sBl, t);
        __syncthreads();

        #pragma unroll
        for (int kk = 0; kk < KC; kk += 16) {
            uint32_t ah[4][4], al[4][4], bh[4][2], bl[4][2];
            #pragma unroll
            for (int mi = 0; mi < 4; mi++) {
                ldfragA(sAh, wm + mi * 16, kk, g, tg, ah[mi]);
                ldfragA(sAl, wm + mi * 16, kk, g, tg, al[mi]);
            }
            #pragma unroll
            for (int ni = 0; ni < 4; ni++) {
                ldfragB(sBh, wn + ni * 8, kk, g, tg, bh[ni]);
                ldfragB(sBl, wn + ni * 8, kk, g, tg, bl[ni]);
            }
            #pragma unroll
            for (int mi = 0; mi < 4; mi++)
                #pragma unroll
                for (int ni = 0; ni < 4; ni++) {
                    mma16816(acc[mi][ni], ah[mi], bh[ni]);
                    mma16816(acc[mi][ni], al[mi], bh[ni]);
                    mma16816(acc[mi][ni], ah[mi], bl[ni]);
                }
        }
        __syncthreads();
    }

    #pragma unroll
    for (int mi = 0; mi < 4; mi++)
        #pragma unroll
        for (int ni = 0; ni < 4; ni++) {
            int r0 = wm + mi * 16 + g;
            int c0 = wn + ni * 8 + tg * 2;
            epi(r0,     c0,     acc[mi][ni][0]);
            epi(r0,     c0 + 1, acc[mi][ni][1]);
            epi(r0 + 8, c0,     acc[mi][ni][2]);
            epi(r0 + 8, c0 + 1, acc[mi][ni][3]);
        }
}

// ============================================================
// Kernel 2: q/k/v = act @ W + b  (warp MMA), epi splits hi/lo (V transposed)
// ============================================================
__global__ void __launch_bounds__(256) qkv_mma_kernel(const float* __restrict__ bq,
                                                      const float* __restrict__ bk,
                                                      const float* __restrict__ bv)
{
    const int z = blockIdx.z;
    const int tile_n = blockIdx.x * 128;
    const int tile_m = blockIdx.y * 128;
    const float* bias = (z == 0) ? bq : (z == 1) ? bk : bv;

    const __nv_bfloat16* Ah = g_acth + (size_t)tile_m * HIDDEN;
    const __nv_bfloat16* Al = g_actl + (size_t)tile_m * HIDDEN;
    const __nv_bfloat16* Bh = g_wth + (size_t)z * HIDDEN * HIDDEN + (size_t)tile_n * HIDDEN;
    const __nv_bfloat16* Bl = g_wtl + (size_t)z * HIDDEN * HIDDEN + (size_t)tile_n * HIDDEN;

    gemm_mma_body(Ah, Al, HIDDEN, Bh, Bl, HIDDEN, HIDDEN,
        [&](int r, int c, float v) {
            int row = tile_m + r, col = tile_n + c;
            float x = v + bias[col];
            __nv_bfloat16 h, l;
            bf16_split(x, h, l);
            if (z == 2) {
                int b = row >> 11, s = row & (SEQ - 1);
                size_t o = ((size_t)b * HIDDEN + col) * SEQ + s;
                g_vth[o] = h; g_vtl[o] = l;
            } else {
                size_t o = (size_t)row * HIDDEN + col;
                if (z == 0) { g_qh[o] = h; g_ql[o] = l; }
                else        { g_kh[o] = h; g_kl[o] = l; }
            }
        });
}

// ============================================================
// Kernel 3: scores = (Q @ K^T) / sqrt(512)  (warp MMA)
// ============================================================
__global__ void __launch_bounds__(256) scores_mma_kernel()
{
    const int z = blockIdx.z;
    const int tile_n = blockIdx.x * 128;
    const int tile_m = blockIdx.y * 128;
    const __nv_bfloat16* Ah = g_qh + ((size_t)z * SEQ + tile_m) * HIDDEN;
    const __nv_bfloat16* Al = g_ql + ((size_t)z * SEQ + tile_m) * HIDDEN;
    const __nv_bfloat16* Bh = g_kh + ((size_t)z * SEQ + tile_n) * HIDDEN;
    const __nv_bfloat16* Bl = g_kl + ((size_t)z * SEQ + tile_n) * HIDDEN;
    float* C = g_scores + (size_t)z * SEQ * SEQ + (size_t)tile_m * SEQ + tile_n;
    const float scale = 0.04419417382415922f;   // 1/sqrt(512)

    gemm_mma_body(Ah, Al, HIDDEN, Bh, Bl, HIDDEN, HIDDEN,
        [&](int r, int c, float v) {
            C[(size_t)r * SEQ + c] = v * scale;
        });
}

// ============================================================
// Kernel 4: row softmax; writes attn bf16 hi/lo
// ============================================================
__global__ void softmax_kernel()
{
    const int row = blockIdx.x;
    const float* p = g_scores + (size_t)row * SEQ;
    __nv_bfloat16* oh = g_ah + (size_t)row * SEQ;
    __nv_bfloat16* ol = g_al + (size_t)row * SEQ;
    const int t = threadIdx.x;
    __shared__ float red[16];

    float v[8];
    float lmax = -1e30f;
    #pragma unroll
    for (int i = 0; i < 8; i++) {
        v[i] = p[t + i * 256];
        lmax = fmaxf(lmax, v[i]);
    }
    #pragma unroll
    for (int o = 16; o; o >>= 1)
        lmax = fmaxf(lmax, __shfl_xor_sync(0xffffffffu, lmax, o));
    if ((t & 31) == 0) red[t >> 5] = lmax;
    __syncthreads();
    float rmax = red[0];
    #pragma unroll
    for (int i = 1; i < 8; i++) rmax = fmaxf(rmax, red[i]);

    float lsum = 0.0f;
    #pragma unroll
    for (int i = 0; i < 8; i++) {
        v[i] = __expf(v[i] - rmax);
        lsum += v[i];
    }
    #pragma unroll
    for (int o = 16; o; o >>= 1)
        lsum += __shfl_xor_sync(0xffffffffu, lsum, o);
    if ((t & 31) == 0) red[8 + (t >> 5)] = lsum;
    __syncthreads();
    float total = 0.0f;
    #pragma unroll
    for (int i = 0; i < 8; i++) total += red[8 + i];

    float inv = 1.0f / total;
    #pragma unroll
    for (int i = 0; i < 8; i++) {
        float pr = v[i] * inv;
        __nv_bfloat16 h, l;
        bf16_split(pr, h, l);
        oh[t + i * 256] = h;
        ol[t + i * 256] = l;
    }
}

// ============================================================
// Kernel 5: out = attn @ V  (warp MMA, B = V^T K-major over tokens)
// ============================================================
__global__ void __launch_bounds__(256) out_mma_kernel(float* __restrict__ out)
{
    const int z = blockIdx.z;
    const int tile_n = blockIdx.x * 128;   // head dim
    const int tile_m = blockIdx.y * 128;   // query pos
    const __nv_bfloat16* Ah = g_ah + (size_t)z * SEQ * SEQ + (size_t)tile_m * SEQ;
    const __nv_bfloat16* Al = g_al + (size_t)z * SEQ * SEQ + (size_t)tile_m * SEQ;
    const __nv_bfloat16* Bh = g_vth + ((size_t)z * HIDDEN + tile_n) * SEQ;
    const __nv_bfloat16* Bl = g_vtl + ((size_t)z * HIDDEN + tile_n) * SEQ;
    float* C = out + ((size_t)z * SEQ + tile_m) * HIDDEN + tile_n;

    gemm_mma_body(Ah, Al, SEQ, Bh, Bl, SEQ, SEQ,
        [&](int r, int c, float v) {
            C[(size_t)r * HIDDEN + c] = v;
        });
}

// ============================================================
// launch
// ============================================================
extern "C" void kernel_launch(void* const* d_in, const int* in_sizes, int n_in,
                              void* d_out, int out_size)
{
    const int*   tok = (const int*)  d_in[0];
    const float* emb = (const float*)d_in[1];
    const float* W1  = (const float*)d_in[2];
    const float* b1  = (const float*)d_in[3];
    const float* Wq  = (const float*)d_in[4];
    const float* bq  = (const float*)d_in[5];
    const float* Wk  = (const float*)d_in[6];
    const float* bk  = (const float*)d_in[7];
    const float* Wv  = (const float*)d_in[8];
    const float* bv  = (const float*)d_in[9];
    float* out = (float*)d_out;

    dim3 blk(256);
    embed_mlp_kernel<<<dim3(HIDDEN / 64, ROWS / 64), blk>>>(tok, emb, W1, b1);
    wsplit_kernel<<<dim3(HIDDEN * HIDDEN / 256, 1, 3), blk>>>(Wq, Wk, Wv);
    qkv_mma_kernel<<<dim3(HIDDEN / 128, ROWS / 128, 3), blk>>>(bq, bk, bv);
    scores_mma_kernel<<<dim3(SEQ / 128, SEQ / 128, BATCH), blk>>>();
    softmax_kernel<<<dim3(ROWS), blk>>>();
    out_mma_kernel<<<dim3(HIDDEN / 128, SEQ / 128, BATCH), blk>>>(out);
}

// round 11
// speedup vs baseline: 2.9144x; 1.2516x over previous
#include <cuda_runtime.h>
#include <cuda_bf16.h>
#include <math.h>
#include <stdint.h>

#define BATCH  4
#define SEQ    2048
#define EMBED  256
#define HIDDEN 512
#define ROWS   (BATCH * SEQ)   // 8192

// -------- scratch (allocation-free: __device__ globals) --------
__device__ __align__(16) __nv_bfloat16 g_acth[ROWS * HIDDEN];            // 8 MB
__device__ __align__(16) __nv_bfloat16 g_actl[ROWS * HIDDEN];
__device__ __align__(16) __nv_bfloat16 g_wth[3 * HIDDEN * HIDDEN];       // W^T hi  [z][n][k]
__device__ __align__(16) __nv_bfloat16 g_wtl[3 * HIDDEN * HIDDEN];
__device__ __align__(16) __nv_bfloat16 g_qh[ROWS * HIDDEN];
__device__ __align__(16) __nv_bfloat16 g_ql[ROWS * HIDDEN];
__device__ __align__(16) __nv_bfloat16 g_kh[ROWS * HIDDEN];
__device__ __align__(16) __nv_bfloat16 g_kl[ROWS * HIDDEN];
__device__ __align__(16) __nv_bfloat16 g_vth[BATCH * HIDDEN * SEQ];      // V^T [b][h][s]
__device__ __align__(16) __nv_bfloat16 g_vtl[BATCH * HIDDEN * SEQ];
__device__ float g_scores[(size_t)BATCH * SEQ * SEQ];                    // 64 MB
__device__ __align__(16) __nv_bfloat16 g_ah[(size_t)BATCH * SEQ * SEQ];  // attn hi
__device__ __align__(16) __nv_bfloat16 g_al[(size_t)BATCH * SEQ * SEQ];  // attn lo

__device__ __forceinline__ void bf16_split(float x, __nv_bfloat16& h, __nv_bfloat16& l) {
    h = __float2bfloat16_rn(x);
    l = __float2bfloat16_rn(x - __bfloat162float(h));
}

// ============================================================
// Kernel 1: act = gelu( emb_table[tok] @ W1 + b1 )  (fp32 SIMT, epi -> bf16 hi/lo)
// ============================================================
__global__ void embed_mlp_kernel(const int* __restrict__ tok,
                                 const float* __restrict__ emb,
                                 const float* __restrict__ W1,
                                 const float* __restrict__ b1)
{
    __shared__ float As[64][17];
    __shared__ float Bs[16][64];

    const int tile_n = blockIdx.x * 64;
    const int tile_m = blockIdx.y * 64;
    const int t  = threadIdx.x;
    const int tx = t & 15;
    const int ty = t >> 4;

    float acc[4][4] = {};

    for (int k0 = 0; k0 < EMBED; k0 += 16) {
        #pragma unroll
        for (int i = 0; i < 4; i++) {
            int idx = t + i * 256;
            int r = idx >> 4, c = idx & 15;
            int token = tok[tile_m + r];
            As[r][c] = emb[(size_t)token * EMBED + k0 + c];
        }
        #pragma unroll
        for (int i = 0; i < 4; i++) {
            int idx = t + i * 256;
            int r = idx >> 6, c = idx & 63;
            Bs[r][c] = W1[(k0 + r) * HIDDEN + tile_n + c];
        }
        __syncthreads();
        #pragma unroll
        for (int kk = 0; kk < 16; kk++) {
            float a[4], b[4];
            #pragma unroll
            for (int i = 0; i < 4; i++) a[i] = As[ty * 4 + i][kk];
            #pragma unroll
            for (int j = 0; j < 4; j++) b[j] = Bs[kk][tx * 4 + j];
            #pragma unroll
            for (int i = 0; i < 4; i++)
                #pragma unroll
                for (int j = 0; j < 4; j++)
                    acc[i][j] = fmaf(a[i], b[j], acc[i][j]);
        }
        __syncthreads();
    }

    #pragma unroll
    for (int i = 0; i < 4; i++) {
        int row = tile_m + ty * 4 + i;
        #pragma unroll
        for (int j = 0; j < 4; j++) {
            int col = tile_n + tx * 4 + j;
            float x = acc[i][j] + b1[col];
            float g = 0.5f * x * (1.0f + erff(x * 0.7071067811865475f));
            __nv_bfloat16 h, l;
            bf16_split(g, h, l);
            size_t o = (size_t)row * HIDDEN + col;
            g_acth[o] = h; g_actl[o] = l;
        }
    }
}

// ============================================================
// Kernel 1b: transpose + hi/lo split of Wq/Wk/Wv -> g_wt{h,l}[z][n][k]
// ============================================================
__global__ void wsplit_kernel(const float* __restrict__ Wq,
                              const float* __restrict__ Wk,
                              const float* __restrict__ Wv)
{
    const int z = blockIdx.z;
    const float* W = (z == 0) ? Wq : (z == 1) ? Wk : Wv;
    int idx = blockIdx.x * 256 + threadIdx.x;       // over 512*512
    int n = idx >> 9, k = idx & 511;
    float x = W[k * HIDDEN + n];
    __nv_bfloat16 h, l;
    bf16_split(x, h, l);
    size_t o = (size_t)z * HIDDEN * HIDDEN + (size_t)n * HIDDEN + k;
    g_wth[o] = h; g_wtl[o] = l;
}

// ============================================================
// Warp-MMA GEMM core (mma.sync m16n8k16 bf16 hi/lo split),
// now with 2-stage cp.async double-buffered pipeline.
// C tile 128x128, 8 warps (2m x 4n), warp tile 64x32, KC=32.
// Smem: 2 stages x 4 tiles x [128][40] bf16 = 81920 B (dynamic).
// ============================================================
#define KC          32
#define SPITCH      40
#define TILE_ELEMS  (128 * SPITCH)          // per tile, bf16 elems
#define STAGE_ELEMS (4 * TILE_ELEMS)
#define SMEM_BYTES  (2 * STAGE_ELEMS * 2)   // 81920

extern __shared__ __nv_bfloat16 dsm[];

__device__ __forceinline__ uint32_t smem_u32(const void* p) {
    uint32_t a;
    asm("{ .reg .u64 t; cvta.to.shared.u64 t, %1; cvt.u32.u64 %0, t; }" : "=r"(a) : "l"(p));
    return a;
}
__device__ __forceinline__ void cp16(uint32_t dst, const void* src) {
    asm volatile("cp.async.cg.shared.global [%0], [%1], 16;" :: "r"(dst), "l"(src));
}
__device__ __forceinline__ void cp_commit() {
    asm volatile("cp.async.commit_group;" ::: "memory");
}
template <int N>
__device__ __forceinline__ void cp_wait() {
    asm volatile("cp.async.wait_group %0;" :: "n"(N) : "memory");
}

__device__ __forceinline__ void mma16816(float c[4], const uint32_t a[4], const uint32_t b[2]) {
    asm volatile(
        "mma.sync.aligned.m16n8k16.row.col.f32.bf16.bf16.f32 "
        "{%0,%1,%2,%3}, {%4,%5,%6,%7}, {%8,%9}, {%0,%1,%2,%3};"
        : "+f"(c[0]), "+f"(c[1]), "+f"(c[2]), "+f"(c[3])
        : "r"(a[0]), "r"(a[1]), "r"(a[2]), "r"(a[3]), "r"(b[0]), "r"(b[1]));
}

__device__ __forceinline__ void ldfragA(const __nv_bfloat16* sA,
                                        int m0, int kk, int g, int tg, uint32_t a[4]) {
    a[0] = *(const uint32_t*)&sA[(m0 + g    ) * SPITCH + kk +     tg * 2];
    a[1] = *(const uint32_t*)&sA[(m0 + g + 8) * SPITCH + kk +     tg * 2];
    a[2] = *(const uint32_t*)&sA[(m0 + g    ) * SPITCH + kk + 8 + tg * 2];
    a[3] = *(const uint32_t*)&sA[(m0 + g + 8) * SPITCH + kk + 8 + tg * 2];
}
__device__ __forceinline__ void ldfragB(const __nv_bfloat16* sB,
                                        int n0, int kk, int g, int tg, uint32_t b[2]) {
    b[0] = *(const uint32_t*)&sB[(n0 + g) * SPITCH + kk +     tg * 2];
    b[1] = *(const uint32_t*)&sB[(n0 + g) * SPITCH + kk + 8 + tg * 2];
}

// async copy of one 128x32 bf16 tile into padded smem tile
__device__ __forceinline__ void copy_tile_async(const __nv_bfloat16* __restrict__ src,
                                                size_t ld, uint32_t dst, int t)
{
    #pragma unroll
    for (int i = 0; i < 2; i++) {
        int idx = t + i * 256;
        int r = idx >> 2, c = idx & 3;
        cp16(dst + (uint32_t)(r * SPITCH + c * 8) * 2,
             src + (size_t)r * ld + c * 8);
    }
}

template <class Epi>
__device__ __forceinline__ void gemm_mma_body(
    const __nv_bfloat16* __restrict__ Ah, const __nv_bfloat16* __restrict__ Al, size_t lda,
    const __nv_bfloat16* __restrict__ Bh, const __nv_bfloat16* __restrict__ Bl, size_t ldb,
    int K, Epi epi)
{
    const int t    = threadIdx.x;
    const int lane = t & 31;
    const int wid  = t >> 5;
    const int wm   = (wid & 1) * 64;      // warp m-offset
    const int wn   = (wid >> 1) * 32;     // warp n-offset
    const int g    = lane >> 2;
    const int tg   = lane & 3;

    const uint32_t sbase = smem_u32(dsm);
    const int kTiles = K / KC;

    float acc[4][4][4] = {};

    // prologue: prefetch stage 0
    {
        uint32_t st = sbase;
        copy_tile_async(Ah, lda, st,                       t);
        copy_tile_async(Al, lda, st + TILE_ELEMS * 2,      t);
        copy_tile_async(Bh, ldb, st + 2 * TILE_ELEMS * 2,  t);
        copy_tile_async(Bl, ldb, st + 3 * TILE_ELEMS * 2,  t);
        cp_commit();
    }

    int s = 0;
    for (int kb = 0; kb < kTiles; kb++) {
        if (kb + 1 < kTiles) {
            const size_t ko = (size_t)(kb + 1) * KC;
            uint32_t st = sbase + (uint32_t)((s ^ 1) * STAGE_ELEMS) * 2;
            copy_tile_async(Ah + ko, lda, st,                      t);
            copy_tile_async(Al + ko, lda, st + TILE_ELEMS * 2,     t);
            copy_tile_async(Bh + ko, ldb, st + 2 * TILE_ELEMS * 2, t);
            copy_tile_async(Bl + ko, ldb, st + 3 * TILE_ELEMS * 2, t);
            cp_commit();
            cp_wait<1>();
        } else {
            cp_wait<0>();
        }
        __syncthreads();

        const __nv_bfloat16* sAh = dsm + s * STAGE_ELEMS;
        const __nv_bfloat16* sAl = sAh + TILE_ELEMS;
        const __nv_bfloat16* sBh = sAh + 2 * TILE_ELEMS;
        const __nv_bfloat16* sBl = sAh + 3 * TILE_ELEMS;

        #pragma unroll
        for (int kk = 0; kk < KC; kk += 16) {
            uint32_t ah[4][4], al[4][4], bh[4][2], bl[4][2];
            #pragma unroll
            for (int mi = 0; mi < 4; mi++) {
                ldfragA(sAh, wm + mi * 16, kk, g, tg, ah[mi]);
                ldfragA(sAl, wm + mi * 16, kk, g, tg, al[mi]);
            }
            #pragma unroll
            for (int ni = 0; ni < 4; ni++) {
                ldfragB(sBh, wn + ni * 8, kk, g, tg, bh[ni]);
                ldfragB(sBl, wn + ni * 8, kk, g, tg, bl[ni]);
            }
            #pragma unroll
            for (int mi = 0; mi < 4; mi++)
                #pragma unroll
                for (int ni = 0; ni < 4; ni++) {
                    mma16816(acc[mi][ni], ah[mi], bh[ni]);
                    mma16816(acc[mi][ni], al[mi], bh[ni]);
                    mma16816(acc[mi][ni], ah[mi], bl[ni]);
                }
        }
        __syncthreads();
        s ^= 1;
    }

    #pragma unroll
    for (int mi = 0; mi < 4; mi++)
        #pragma unroll
        for (int ni = 0; ni < 4; ni++) {
            int r0 = wm + mi * 16 + g;
            int c0 = wn + ni * 8 + tg * 2;
            epi(r0,     c0,     acc[mi][ni][0]);
            epi(r0,     c0 + 1, acc[mi][ni][1]);
            epi(r0 + 8, c0,     acc[mi][ni][2]);
            epi(r0 + 8, c0 + 1, acc[mi][ni][3]);
        }
}

// ============================================================
// Kernel 2: q/k/v = act @ W + b  (warp MMA), epi splits hi/lo (V transposed)
// ============================================================
__global__ void __launch_bounds__(256) qkv_mma_kernel(const float* __restrict__ bq,
                                                      const float* __restrict__ bk,
                                                      const float* __restrict__ bv)
{
    const int z = blockIdx.z;
    const int tile_n = blockIdx.x * 128;
    const int tile_m = blockIdx.y * 128;
    const float* bias = (z == 0) ? bq : (z == 1) ? bk : bv;

    const __nv_bfloat16* Ah = g_acth + (size_t)tile_m * HIDDEN;
    const __nv_bfloat16* Al = g_actl + (size_t)tile_m * HIDDEN;
    const __nv_bfloat16* Bh = g_wth + (size_t)z * HIDDEN * HIDDEN + (size_t)tile_n * HIDDEN;
    const __nv_bfloat16* Bl = g_wtl + (size_t)z * HIDDEN * HIDDEN + (size_t)tile_n * HIDDEN;

    gemm_mma_body(Ah, Al, HIDDEN, Bh, Bl, HIDDEN, HIDDEN,
        [&](int r, int c, float v) {
            int row = tile_m + r, col = tile_n + c;
            float x = v + bias[col];
            __nv_bfloat16 h, l;
            bf16_split(x, h, l);
            if (z == 2) {
                int b = row >> 11, s = row & (SEQ - 1);
                size_t o = ((size_t)b * HIDDEN + col) * SEQ + s;
                g_vth[o] = h; g_vtl[o] = l;
            } else {
                size_t o = (size_t)row * HIDDEN + col;
                if (z == 0) { g_qh[o] = h; g_ql[o] = l; }
                else        { g_kh[o] = h; g_kl[o] = l; }
            }
        });
}

// ============================================================
// Kernel 3: scores = (Q @ K^T) / sqrt(512)  (warp MMA)
// ============================================================
__global__ void __launch_bounds__(256) scores_mma_kernel()
{
    const int z = blockIdx.z;
    const int tile_n = blockIdx.x * 128;
    const int tile_m = blockIdx.y * 128;
    const __nv_bfloat16* Ah = g_qh + ((size_t)z * SEQ + tile_m) * HIDDEN;
    const __nv_bfloat16* Al = g_ql + ((size_t)z * SEQ + tile_m) * HIDDEN;
    const __nv_bfloat16* Bh = g_kh + ((size_t)z * SEQ + tile_n) * HIDDEN;
    const __nv_bfloat16* Bl = g_kl + ((size_t)z * SEQ + tile_n) * HIDDEN;
    float* C = g_scores + (size_t)z * SEQ * SEQ + (size_t)tile_m * SEQ + tile_n;
    const float scale = 0.04419417382415922f;   // 1/sqrt(512)

    gemm_mma_body(Ah, Al, HIDDEN, Bh, Bl, HIDDEN, HIDDEN,
        [&](int r, int c, float v) {
            C[(size_t)r * SEQ + c] = v * scale;
        });
}

// ============================================================
// Kernel 4: row softmax; writes attn bf16 hi/lo
// ============================================================
__global__ void softmax_kernel()
{
    const int row = blockIdx.x;
    const float* p = g_scores + (size_t)row * SEQ;
    __nv_bfloat16* oh = g_ah + (size_t)row * SEQ;
    __nv_bfloat16* ol = g_al + (size_t)row * SEQ;
    const int t = threadIdx.x;
    __shared__ float red[16];

    float v[8];
    float lmax = -1e30f;
    #pragma unroll
    for (int i = 0; i < 8; i++) {
        v[i] = p[t + i * 256];
        lmax = fmaxf(lmax, v[i]);
    }
    #pragma unroll
    for (int o = 16; o; o >>= 1)
        lmax = fmaxf(lmax, __shfl_xor_sync(0xffffffffu, lmax, o));
    if ((t & 31) == 0) red[t >> 5] = lmax;
    __syncthreads();
    float rmax = red[0];
    #pragma unroll
    for (int i = 1; i < 8; i++) rmax = fmaxf(rmax, red[i]);

    float lsum = 0.0f;
    #pragma unroll
    for (int i = 0; i < 8; i++) {
        v[i] = __expf(v[i] - rmax);
        lsum += v[i];
    }
    #pragma unroll
    for (int o = 16; o; o >>= 1)
        lsum += __shfl_xor_sync(0xffffffffu, lsum, o);
    if ((t & 31) == 0) red[8 + (t >> 5)] = lsum;
    __syncthreads();
    float total = 0.0f;
    #pragma unroll
    for (int i = 0; i < 8; i++) total += red[8 + i];

    float inv = 1.0f / total;
    #pragma unroll
    for (int i = 0; i < 8; i++) {
        float pr = v[i] * inv;
        __nv_bfloat16 h, l;
        bf16_split(pr, h, l);
        oh[t + i * 256] = h;
        ol[t + i * 256] = l;
    }
}

// ============================================================
// Kernel 5: out = attn @ V  (warp MMA, B = V^T K-major over tokens)
// ============================================================
__global__ void __launch_bounds__(256) out_mma_kernel(float* __restrict__ out)
{
    const int z = blockIdx.z;
    const int tile_n = blockIdx.x * 128;   // head dim
    const int tile_m = blockIdx.y * 128;   // query pos
    const __nv_bfloat16* Ah = g_ah + (size_t)z * SEQ * SEQ + (size_t)tile_m * SEQ;
    const __nv_bfloat16* Al = g_al + (size_t)z * SEQ * SEQ + (size_t)tile_m * SEQ;
    const __nv_bfloat16* Bh = g_vth + ((size_t)z * HIDDEN + tile_n) * SEQ;
    const __nv_bfloat16* Bl = g_vtl + ((size_t)z * HIDDEN + tile_n) * SEQ;
    float* C = out + ((size_t)z * SEQ + tile_m) * HIDDEN + tile_n;

    gemm_mma_body(Ah, Al, SEQ, Bh, Bl, SEQ, SEQ,
        [&](int r, int c, float v) {
            C[(size_t)r * HIDDEN + c] = v;
        });
}

// ============================================================
// launch
// ============================================================
extern "C" void kernel_launch(void* const* d_in, const int* in_sizes, int n_in,
                              void* d_out, int out_size)
{
    const int*   tok = (const int*)  d_in[0];
    const float* emb = (const float*)d_in[1];
    const float* W1  = (const float*)d_in[2];
    const float* b1  = (const float*)d_in[3];
    const float* Wq  = (const float*)d_in[4];
    const float* bq  = (const float*)d_in[5];
    const float* Wk  = (const float*)d_in[6];
    const float* bk  = (const float*)d_in[7];
    const float* Wv  = (const float*)d_in[8];
    const float* bv  = (const float*)d_in[9];
    float* out = (float*)d_out;

    static int smem_set = 0;
    if (!smem_set) {
        (void)cudaFuncSetAttribute(qkv_mma_kernel,
                                   cudaFuncAttributeMaxDynamicSharedMemorySize, SMEM_BYTES);
        (void)cudaFuncSetAttribute(scores_mma_kernel,
                                   cudaFuncAttributeMaxDynamicSharedMemorySize, SMEM_BYTES);
        (void)cudaFuncSetAttribute(out_mma_kernel,
                                   cudaFuncAttributeMaxDynamicSharedMemorySize, SMEM_BYTES);
        smem_set = 1;
    }

    dim3 blk(256);
    embed_mlp_kernel<<<dim3(HIDDEN / 64, ROWS / 64), blk>>>(tok, emb, W1, b1);
    wsplit_kernel<<<dim3(HIDDEN * HIDDEN / 256, 1, 3), blk>>>(Wq, Wk, Wv);
    qkv_mma_kernel<<<dim3(HIDDEN / 128, ROWS / 128, 3), blk, SMEM_BYTES>>>(bq, bk, bv);
    scores_mma_kernel<<<dim3(SEQ / 128, SEQ / 128, BATCH), blk, SMEM_BYTES>>>();
    softmax_kernel<<<dim3(ROWS), blk>>>();
    out_mma_kernel<<<dim3(HIDDEN / 128, SEQ / 128, BATCH), blk, SMEM_BYTES>>>(out);
}